// round 8
// baseline (speedup 1.0000x reference)
#include <cuda_runtime.h>

// EmbeddingLayer: 16 sparse gathers + 2 sequence poolings (sum, nonzero-mean) + dense concat.
//
// R8 = R6 (grid 5120, pooling blocks first, shuffle-distributed indices)
//      with the pooling gathers converted to a cp.async (LDGSTS) double-
//      buffered pipeline: outstanding copies cost ZERO registers, breaking
//      the register-MLP ceiling that pinned R4/R6/R7 at ~19us.
//   Each thread stages its own 16B slice into its own smem slot and reads
//   only what it wrote -> cp.async.wait_group is the only ordering needed.

#define VOCAB   100000
#define BATCH   4096
#define EMBED   64
#define SEQLEN  50
#define NSPARSE 16
#define NDENSE  13
#define ROW_OUT (NSPARSE * EMBED + 2 * EMBED + NDENSE)  // 1165

#define SEQ_ROWS_PER_BLOCK 4                          // 4 rows x 2 feats = 8 warps
#define SEQ_BLOCKS (BATCH / SEQ_ROWS_PER_BLOCK)       // 1024  (blockIdx 0..1023)
#define SPARSE_BLOCKS BATCH                           // 4096
#define THREADS 256
#define HALF_SEQ (SEQLEN / 2)                         // 25
#define N_CHUNKS 5
#define ITERS_PER_CHUNK 5                             // 5 s-values = 10 rows per chunk

__device__ __forceinline__ void cp16(float4* smem_dst, const float4* gsrc) {
    unsigned saddr = (unsigned)__cvta_generic_to_shared(smem_dst);
    asm volatile("cp.async.cg.shared.global [%0], [%1], 16;"
                 :: "r"(saddr), "l"(gsrc));
}

__global__ __launch_bounds__(THREADS, 5)
void embedding_layer_kernel(const float4* __restrict__ sp_tab,   // [16*VOCAB*16] float4
                            const float4* __restrict__ seq_tab,  // [ 2*VOCAB*16] float4
                            const float*  __restrict__ dense,    // [BATCH*13]
                            const int*    __restrict__ sp_idx,   // [16*BATCH]
                            const int*    __restrict__ sq_idx,   // [2*BATCH*50]
                            float*        __restrict__ out)      // [BATCH*1165]
{
    // [warp][buf][iter][half][q] : 8*2*5*2*16 float4 = 40KB
    __shared__ float4 s_buf[8][2][ITERS_PER_CHUNK][2][16];

    const int tid = threadIdx.x;

    if (blockIdx.x < SEQ_BLOCKS) {
        // ---- seq pooling: one warp per (batch row, feature) ----
        const int w    = tid >> 5;                       // warp 0..7
        const int lane = tid & 31;
        const int b    = blockIdx.x * SEQ_ROWS_PER_BLOCK + (w >> 1);
        const int feat = w & 1;                          // 0: sum, 1: nonzero-mean
        const int q    = lane & 15;                      // float4 lane in embed dim
        const int half = lane >> 4;                      // 0 -> s'=[0,25), 1 -> s'=[25,50)

        const int* __restrict__ ip =
            sq_idx + ((size_t)feat * BATCH + b) * SEQLEN;
        const float4* __restrict__ tab = seq_tab + (size_t)feat * VOCAB * 16;

        // cooperative index load: lane l holds ip[l]; lanes 0..17 also ip[32+l]
        int idx_a = __ldg(&ip[lane]);
        int idx_b = (lane < SEQLEN - 32) ? __ldg(&ip[32 + lane]) : 0;

        // idx for seq position s' = half*25 + s, via warp shuffle
        auto get_idx = [&](int s) -> int {
            if (s < 7) {
                int sp = half ? (s + 25) : s;
                return __shfl_sync(0xFFFFFFFFu, idx_a, sp);
            } else {
                int va = __shfl_sync(0xFFFFFFFFu, idx_a, s);
                int vb = __shfl_sync(0xFFFFFFFFu, idx_b, s - 7);  // 32+(s-7)=s+25
                return half ? vb : va;
            }
        };

        // issue one chunk (5 iters x this thread's 16B slice) into buffer pb
        auto issue = [&](int c, int pb) {
            #pragma unroll
            for (int it = 0; it < ITERS_PER_CHUNK; it++) {
                int idx = get_idx(c * ITERS_PER_CHUNK + it);
                cp16(&s_buf[w][pb][it][half][q], &tab[(size_t)idx * 16 + q]);
            }
            asm volatile("cp.async.commit_group;");
        };

        float4 acc = make_float4(0.f, 0.f, 0.f, 0.f);
        float4 cnt = make_float4(0.f, 0.f, 0.f, 0.f);

        issue(0, 0);
        issue(1, 1);

        #pragma unroll
        for (int c = 0; c < N_CHUNKS; c++) {
            if (c < N_CHUNKS - 1)
                asm volatile("cp.async.wait_group 1;");
            else
                asm volatile("cp.async.wait_group 0;");

            const int pb = c & 1;
            #pragma unroll
            for (int it = 0; it < ITERS_PER_CHUNK; it++) {
                float4 v = s_buf[w][pb][it][half][q];
                acc.x += v.x; acc.y += v.y; acc.z += v.z; acc.w += v.w;
                if (feat) {
                    cnt.x += (v.x != 0.f) ? 1.f : 0.f;
                    cnt.y += (v.y != 0.f) ? 1.f : 0.f;
                    cnt.z += (v.z != 0.f) ? 1.f : 0.f;
                    cnt.w += (v.w != 0.f) ? 1.f : 0.f;
                }
            }
            if (c < N_CHUNKS - 2)
                issue(c + 2, pb);
        }

        // merge the two seq-halves (lanes l and l^16 share q)
        acc.x += __shfl_xor_sync(0xFFFFFFFFu, acc.x, 16);
        acc.y += __shfl_xor_sync(0xFFFFFFFFu, acc.y, 16);
        acc.z += __shfl_xor_sync(0xFFFFFFFFu, acc.z, 16);
        acc.w += __shfl_xor_sync(0xFFFFFFFFu, acc.w, 16);
        if (feat) {
            cnt.x += __shfl_xor_sync(0xFFFFFFFFu, cnt.x, 16);
            cnt.y += __shfl_xor_sync(0xFFFFFFFFu, cnt.y, 16);
            cnt.z += __shfl_xor_sync(0xFFFFFFFFu, cnt.z, 16);
            cnt.w += __shfl_xor_sync(0xFFFFFFFFu, cnt.w, 16);
        }

        if (half == 0) {
            float* o = out + (size_t)b * ROW_OUT + (NSPARSE + feat) * EMBED + q * 4;
            if (feat == 0) {
                o[0] = acc.x; o[1] = acc.y; o[2] = acc.z; o[3] = acc.w;
            } else {
                o[0] = acc.x / (cnt.x + 1e-16f);
                o[1] = acc.y / (cnt.y + 1e-16f);
                o[2] = acc.z / (cnt.z + 1e-16f);
                o[3] = acc.w / (cnt.w + 1e-16f);
            }
        }
    } else {
        // ---- sparse copy + dense tail: one block per batch row ----
        const int b = blockIdx.x - SEQ_BLOCKS;
        const int f = tid >> 4;      // feature 0..15
        const int q = tid & 15;      // float4 lane 0..15

        float* __restrict__ orow = out + (size_t)b * ROW_OUT;

        int idx = __ldg(&sp_idx[f * BATCH + b]);
        float4 v = __ldg(&sp_tab[((size_t)f * VOCAB + idx) * 16 + q]);
        float* o = orow + f * EMBED + q * 4;
        o[0] = v.x; o[1] = v.y; o[2] = v.z; o[3] = v.w;

        if (tid < NDENSE)
            orow[(NSPARSE + 2) * EMBED + tid] = __ldg(&dense[(size_t)b * NDENSE + tid]);
    }
}

extern "C" void kernel_launch(void* const* d_in, const int* in_sizes, int n_in,
                              void* d_out, int out_size) {
    const float* sp_tab  = (const float*)d_in[0];
    const float* seq_tab = (const float*)d_in[1];
    const float* dense   = (const float*)d_in[2];
    const int*   sp_idx  = (const int*)d_in[3];
    const int*   sq_idx  = (const int*)d_in[4];
    float*       out     = (float*)d_out;

    dim3 grid(SEQ_BLOCKS + SPARSE_BLOCKS);  // 5120 blocks, pooling first
    dim3 block(THREADS);
    embedding_layer_kernel<<<grid, block>>>(
        (const float4*)sp_tab, (const float4*)seq_tab, dense, sp_idx, sq_idx, out);
}

// round 10
// speedup vs baseline: 1.0864x; 1.0864x over previous
#include <cuda_runtime.h>
#include <cstdint>

// EmbeddingLayer: 16 sparse gathers + 2 sequence poolings (sum, nonzero-mean) + dense concat.
//
// R10 = R9 retry with the ptxas-legal evict_last encoding:
//   createpolicy.fractional.L2::evict_last.b64  +  ld.global.nc.L2::cache_hint
//   (inline ".L2::evict_last" qualifier is only legal on 32B vector loads on
//   sm_103a; cache_hint + policy register works for .v4.f32 / .s32).
//   - seq-table gathers + seq index loads: evict_last (pin ~45MB hot set in L2)
//   - sparse-table gathers: __ldcs (evict-first)
//   - output stores: __stcs (streaming)

#define VOCAB   100000
#define BATCH   4096
#define EMBED   64
#define SEQLEN  50
#define NSPARSE 16
#define NDENSE  13
#define ROW_OUT (NSPARSE * EMBED + 2 * EMBED + NDENSE)  // 1165

#define SEQ_ROWS_PER_BLOCK 4                          // 4 rows x 2 feats = 8 warps
#define SEQ_BLOCKS (BATCH / SEQ_ROWS_PER_BLOCK)       // 1024  (blockIdx 0..1023)
#define SPARSE_BLOCKS BATCH                           // 4096
#define THREADS 256
#define HALF_SEQ (SEQLEN / 2)                         // 25

__device__ __forceinline__ uint64_t evict_last_policy() {
    uint64_t p;
    asm("createpolicy.fractional.L2::evict_last.b64 %0, 1.0;" : "=l"(p));
    return p;
}
__device__ __forceinline__ float4 ldg_el(const float4* p, uint64_t pol) {
    float4 v;
    asm volatile("ld.global.nc.L2::cache_hint.v4.f32 {%0,%1,%2,%3}, [%4], %5;"
                 : "=f"(v.x), "=f"(v.y), "=f"(v.z), "=f"(v.w)
                 : "l"(p), "l"(pol));
    return v;
}
__device__ __forceinline__ int ldg_el_i(const int* p, uint64_t pol) {
    int v;
    asm volatile("ld.global.nc.L2::cache_hint.s32 %0, [%1], %2;"
                 : "=r"(v) : "l"(p), "l"(pol));
    return v;
}

__global__ __launch_bounds__(THREADS, 5)
void embedding_layer_kernel(const float4* __restrict__ sp_tab,   // [16*VOCAB*16] float4
                            const float4* __restrict__ seq_tab,  // [ 2*VOCAB*16] float4
                            const float*  __restrict__ dense,    // [BATCH*13]
                            const int*    __restrict__ sp_idx,   // [16*BATCH]
                            const int*    __restrict__ sq_idx,   // [2*BATCH*50]
                            float*        __restrict__ out)      // [BATCH*1165]
{
    const int tid = threadIdx.x;

    if (blockIdx.x < SEQ_BLOCKS) {
        // ---- seq pooling: one warp per (batch row, feature) ----
        const int warp = tid >> 5;                       // 0..7
        const int lane = tid & 31;
        const int b    = blockIdx.x * SEQ_ROWS_PER_BLOCK + (warp >> 1);
        const int feat = warp & 1;                       // 0: sum, 1: nonzero-mean
        const int q    = lane & 15;                      // float4 lane in embed dim
        const int half = lane >> 4;                      // 0 -> s'=[0,25), 1 -> s'=[25,50)

        const uint64_t pol = evict_last_policy();

        const int* __restrict__ ip =
            sq_idx + ((size_t)feat * BATCH + b) * SEQLEN;
        const float4* __restrict__ tab = seq_tab + (size_t)feat * VOCAB * 16;

        // cooperative index load: lane l holds ip[l]; lanes 0..17 also ip[32+l]
        int idx_a = ldg_el_i(&ip[lane], pol);
        int idx_b = (lane < SEQLEN - 32) ? ldg_el_i(&ip[32 + lane], pol) : 0;

        float4 acc = make_float4(0.f, 0.f, 0.f, 0.f);
        float4 cnt = make_float4(0.f, 0.f, 0.f, 0.f);

        #pragma unroll
        for (int s = 0; s < HALF_SEQ; s++) {
            int idx;
            if (s < 7) {
                int sp = half ? (s + 25) : s;
                idx = __shfl_sync(0xFFFFFFFFu, idx_a, sp);
            } else {
                int va = __shfl_sync(0xFFFFFFFFu, idx_a, s);
                int vb = __shfl_sync(0xFFFFFFFFu, idx_b, s - 7);  // 32+(s-7)=s+25
                idx = half ? vb : va;
            }
            float4 v = ldg_el(&tab[(size_t)idx * 16 + q], pol);   // pin seq rows in L2
            acc.x += v.x; acc.y += v.y; acc.z += v.z; acc.w += v.w;
            if (feat) {
                cnt.x += (v.x != 0.f) ? 1.f : 0.f;
                cnt.y += (v.y != 0.f) ? 1.f : 0.f;
                cnt.z += (v.z != 0.f) ? 1.f : 0.f;
                cnt.w += (v.w != 0.f) ? 1.f : 0.f;
            }
        }

        // merge the two seq-halves (lanes l and l^16 share q)
        acc.x += __shfl_xor_sync(0xFFFFFFFFu, acc.x, 16);
        acc.y += __shfl_xor_sync(0xFFFFFFFFu, acc.y, 16);
        acc.z += __shfl_xor_sync(0xFFFFFFFFu, acc.z, 16);
        acc.w += __shfl_xor_sync(0xFFFFFFFFu, acc.w, 16);
        if (feat) {
            cnt.x += __shfl_xor_sync(0xFFFFFFFFu, cnt.x, 16);
            cnt.y += __shfl_xor_sync(0xFFFFFFFFu, cnt.y, 16);
            cnt.z += __shfl_xor_sync(0xFFFFFFFFu, cnt.z, 16);
            cnt.w += __shfl_xor_sync(0xFFFFFFFFu, cnt.w, 16);
        }

        if (half == 0) {
            float* o = out + (size_t)b * ROW_OUT + (NSPARSE + feat) * EMBED + q * 4;
            if (feat == 0) {
                __stcs(&o[0], acc.x); __stcs(&o[1], acc.y);
                __stcs(&o[2], acc.z); __stcs(&o[3], acc.w);
            } else {
                __stcs(&o[0], acc.x / (cnt.x + 1e-16f));
                __stcs(&o[1], acc.y / (cnt.y + 1e-16f));
                __stcs(&o[2], acc.z / (cnt.z + 1e-16f));
                __stcs(&o[3], acc.w / (cnt.w + 1e-16f));
            }
        }
    } else {
        // ---- sparse copy + dense tail: one block per batch row ----
        const int b = blockIdx.x - SEQ_BLOCKS;
        const int f = tid >> 4;      // feature 0..15
        const int q = tid & 15;      // float4 lane 0..15

        float* __restrict__ orow = out + (size_t)b * ROW_OUT;

        int idx = __ldg(&sp_idx[f * BATCH + b]);
        // evict-first: must not displace the pinned seq set
        float4 v = __ldcs(&sp_tab[((size_t)f * VOCAB + idx) * 16 + q]);
        float* o = orow + f * EMBED + q * 4;
        __stcs(&o[0], v.x); __stcs(&o[1], v.y);
        __stcs(&o[2], v.z); __stcs(&o[3], v.w);

        if (tid < NDENSE)
            __stcs(&orow[(NSPARSE + 2) * EMBED + tid],
                   __ldg(&dense[(size_t)b * NDENSE + tid]));
    }
}

extern "C" void kernel_launch(void* const* d_in, const int* in_sizes, int n_in,
                              void* d_out, int out_size) {
    const float* sp_tab  = (const float*)d_in[0];
    const float* seq_tab = (const float*)d_in[1];
    const float* dense   = (const float*)d_in[2];
    const int*   sp_idx  = (const int*)d_in[3];
    const int*   sq_idx  = (const int*)d_in[4];
    float*       out     = (float*)d_out;

    dim3 grid(SEQ_BLOCKS + SPARSE_BLOCKS);  // 5120 blocks, pooling first
    dim3 block(THREADS);
    embedding_layer_kernel<<<grid, block>>>(
        (const float4*)sp_tab, (const float4*)seq_tab, dense, sp_idx, sq_idx, out);
}